// round 2
// baseline (speedup 1.0000x reference)
#include <cuda_runtime.h>
#include <math.h>

// Problem shape (fixed by the benchmark reference)
#define NB 4
#define NG 1024
#define NT 1024
#define NK 5
#define NC 8

// Tiling
#define T_TILE 28          // t's per CTA (37*28 = 1036 >= 1024)
#define N_TTILES 37
#define G_SPLIT 2          // split grid-axis reduction over 2 CTAs
#define GH (NG / G_SPLIT)  // 512 g's staged per CTA
#define TLH 14             // t-lanes per block; each thread owns t and t+TLH
#define BLOCK (TLH * NC)   // 112 threads

#define SMEM_FLOATS (GH*NC + GH*NK*NC + NK*NC + NC)   // x tile + h tile + m[k][c] + uniform flags

__device__ __forceinline__ float ex2f(float x) {
    float r; asm("ex2.approx.ftz.f32 %0, %1;" : "=f"(r) : "f"(x)); return r;
}

__global__ void zero_out_kernel(float* __restrict__ out, int n) {
    int i = blockIdx.x * blockDim.x + threadIdx.x;
    if (i < n) out[i] = 0.0f;
}

__global__ __launch_bounds__(BLOCK) void gauss_kernel(
    const float* __restrict__ x_grid,   // (b, g, c)
    const float* __restrict__ h_grid,   // (b, g, k, c)
    const float* __restrict__ target_x, // (b, t, c)
    const float* __restrict__ sigma,    // (k, c)
    float* __restrict__ out)            // (b, t, k, c)
{
    extern __shared__ float sm[];
    float* xs = sm;                     // GH*NC
    float* hs = xs + GH*NC;             // GH*NK*NC
    float* ms = hs + GH*NK*NC;          // NK*NC  : m[k][c] = -0.5*log2(e)/(exp(sigma)+eps)^2
    float* uf = ms + NK*NC;             // NC     : per-channel "all k scales equal" flag

    const int gh   = blockIdx.x;   // which g-half
    const int tile = blockIdx.y;   // t tile
    const int b    = blockIdx.z;   // batch
    const int tid  = threadIdx.x;

    // Per-(k,c) exponent multiplier from sigma (matches reference: exp(sigma)+EPS)
    if (tid < NK*NC) {
        float s = expf(sigma[tid]) + 1e-6f;
        ms[tid] = -0.72134752044448170f / (s*s);   // -0.5 * log2(e) / s^2
    }
    __syncthreads();
    // Runtime uniformity detection per channel (exact float equality; deterministic)
    if (tid < NC) {
        float m0 = ms[tid];
        int u = 1;
        #pragma unroll
        for (int k = 1; k < NK; ++k) u = u && (ms[k*NC + tid] == m0);
        uf[tid] = (float)u;
    }

    // Stage this CTA's g-half of x and h into shared memory (vectorized, batched for MLP)
    const float4* xg4 = (const float4*)(x_grid + ((size_t)b*NG + (size_t)gh*GH)*NC);
    const float4* hg4 = (const float4*)(h_grid + ((size_t)b*NG + (size_t)gh*GH)*(size_t)(NK*NC));
    float4* xs4 = (float4*)xs;
    float4* hs4 = (float4*)hs;
    {
        // x tile: GH*NC/4 = 1024 float4 over 112 threads
        #pragma unroll
        for (int r = 0; r < 10; ++r) {
            int i = tid + r*BLOCK;
            if (i < GH*NC/4) xs4[i] = xg4[i];
        }
        // h tile: GH*NK*NC/4 = 5120 float4 over 112 threads; batch 8 loads per iter for MLP
        #pragma unroll
        for (int r = 0; r < 46; ++r) {
            int i = tid + r*BLOCK;
            if (i < GH*NK*NC/4) hs4[i] = hg4[i];
        }
    }
    __syncthreads();

    const int c  = tid & (NC-1);
    const int tl = tid >> 3;
    const int t0 = tile*T_TILE + tl;
    const int t1 = t0 + TLH;

    float y0 = 0.0f, y1 = 0.0f;
    if (t0 < NT) y0 = target_x[((size_t)b*NT + t0)*NC + c];
    if (t1 < NT) y1 = target_x[((size_t)b*NT + t1)*NC + c];

    float acc0[NK], acc1[NK];
    #pragma unroll
    for (int k = 0; k < NK; ++k) { acc0[k] = 0.0f; acc1[k] = 0.0f; }

    float mk[NK];
    #pragma unroll
    for (int k = 0; k < NK; ++k) mk[k] = ms[k*NC + c];
    const bool uni = (uf[c] != 0.0f);

    if (uni) {
        // Fast path: one exp serves all 5 basis functions -> FFMA-bound
        const float m0 = mk[0];
        #pragma unroll 4
        for (int g = 0; g < GH; ++g) {
            const float xv = xs[g*NC + c];
            const float d0 = xv - y0;
            const float d1 = xv - y1;
            const float e0 = ex2f(d0*d0*m0);
            const float e1 = ex2f(d1*d1*m0);
            const float* hp = hs + g*(NK*NC) + c;
            #pragma unroll
            for (int k = 0; k < NK; ++k) {
                const float h = hp[k*NC];
                acc0[k] = fmaf(e0, h, acc0[k]);
                acc1[k] = fmaf(e1, h, acc1[k]);
            }
        }
    } else {
        // General path: per-k exp (MUFU-bound)
        #pragma unroll 2
        for (int g = 0; g < GH; ++g) {
            const float xv = xs[g*NC + c];
            const float d0 = xv - y0;
            const float d1 = xv - y1;
            const float a0 = d0*d0;
            const float a1 = d1*d1;
            const float* hp = hs + g*(NK*NC) + c;
            #pragma unroll
            for (int k = 0; k < NK; ++k) {
                const float h = hp[k*NC];
                acc0[k] = fmaf(ex2f(a0*mk[k]), h, acc0[k]);
                acc1[k] = fmaf(ex2f(a1*mk[k]), h, acc1[k]);
            }
        }
    }

    // Combine the two g-halves with atomics (2 commutative adds onto 0 -> deterministic result)
    if (t0 < NT) {
        float* o = out + (((size_t)b*NT + t0)*NK)*NC + c;
        #pragma unroll
        for (int k = 0; k < NK; ++k) atomicAdd(o + k*NC, acc0[k]);
    }
    if (t1 < NT) {
        float* o = out + (((size_t)b*NT + t1)*NK)*NC + c;
        #pragma unroll
        for (int k = 0; k < NK; ++k) atomicAdd(o + k*NC, acc1[k]);
    }
}

extern "C" void kernel_launch(void* const* d_in, const int* in_sizes, int n_in,
                              void* d_out, int out_size) {
    const float* x_grid  = (const float*)d_in[0];
    const float* h_grid  = (const float*)d_in[1];
    const float* target  = (const float*)d_in[2];
    const float* sigma   = (const float*)d_in[3];
    float* out = (float*)d_out;

    size_t smem = SMEM_FLOATS * sizeof(float);   // 98496 B -> 2 CTAs/SM
    cudaFuncSetAttribute(gauss_kernel, cudaFuncAttributeMaxDynamicSharedMemorySize, (int)smem);

    zero_out_kernel<<<(out_size + 255) / 256, 256>>>(out, out_size);

    dim3 grid(G_SPLIT, N_TTILES, NB);
    gauss_kernel<<<grid, BLOCK, smem>>>(x_grid, h_grid, target, sigma, out);
}